// round 15
// baseline (speedup 1.0000x reference)
#include <cuda_runtime.h>
#include <cstdint>

// ============================ problem constants ============================
#define TILE_P 128
#define SSEG   16384          // B*D = 256*64
#define FDIM   64
#define NTHREADS 256
#define GRID_MAIN 148

// ============================ scratch globals ==============================
__device__ __align__(16) float g_seg_t[SSEG * 32];
__device__ __align__(16) float g_seg_r[SSEG * 32];

// ============================ smem layout (bytes) ==========================
// X:   [128 p][68 f32]  (row stride 272B, 64 used)      -> 34816
// H1:  [128 p][132 f32] (row stride 528B, 128 used)     -> 67584
// W1P: 2 br x [32 n][136 f32] pair-packed               -> 34816
// W0P: [br][warp_n][ks*4+nb][lane] uint2 (8192 uint2)   -> 65536
// H2:  single branch [128 p][32 f32]                    -> 16384
#define SM_X    0
#define SM_H1   34816
#define SM_W1P  102400
#define SM_W0P  137216
#define SM_H2   202752
#define SM_SID  219136
#define SM_B0   219648
#define SM_B1   220672
#define SMEM_BYTES 220928

#define XSTRIDE  68
#define H1STRIDE 132
#define W1STRIDE 136

// ============================ PTX helpers ==================================
__device__ __forceinline__ uint32_t smem_u32(const void* p) {
    uint32_t a;
    asm("{ .reg .u64 t; cvta.to.shared.u64 t, %1; cvt.u32.u64 %0, t; }"
        : "=r"(a) : "l"(p));
    return a;
}
__device__ __forceinline__ void ldsm_x4(uint32_t* r, uint32_t a) {
    asm volatile("ldmatrix.sync.aligned.m8n8.x4.shared.b16 {%0,%1,%2,%3}, [%4];"
                 : "=r"(r[0]), "=r"(r[1]), "=r"(r[2]), "=r"(r[3]) : "r"(a));
}
__device__ __forceinline__ void mma_tf32(float* d, const uint32_t* a,
                                         uint32_t b0, uint32_t b1) {
    asm volatile(
        "mma.sync.aligned.m16n8k8.row.col.f32.tf32.tf32.f32 "
        "{%0,%1,%2,%3}, {%4,%5,%6,%7}, {%8,%9}, {%0,%1,%2,%3};"
        : "+f"(d[0]), "+f"(d[1]), "+f"(d[2]), "+f"(d[3])
        : "r"(a[0]), "r"(a[1]), "r"(a[2]), "r"(a[3]), "r"(b0), "r"(b1));
}
__device__ __forceinline__ uint32_t f2tf(float v) {
    uint32_t r;
    asm("cvt.rna.tf32.f32 %0, %1;" : "=r"(r) : "f"(v));
    return r;
}

// ============================ small kernels ================================
__global__ void zero_seg_kernel() {
    int i = blockIdx.x * blockDim.x + threadIdx.x;
    if (i < SSEG * 32) { g_seg_t[i] = 0.f; g_seg_r[i] = 0.f; }
}

// ============================ main persistent kernel =======================
__global__ __launch_bounds__(NTHREADS, 1)
void mlp_mma_kernel(const float* __restrict__ x, const int* __restrict__ seg,
                    const float* __restrict__ w0t, const float* __restrict__ w0r,
                    const float* __restrict__ w1t, const float* __restrict__ w1r,
                    const float* __restrict__ b0t, const float* __restrict__ b0r,
                    const float* __restrict__ b1t, const float* __restrict__ b1r,
                    int N) {
    extern __shared__ char smem[];
    uint32_t sb = smem_u32(smem);
    int tid = threadIdx.x, lane = tid & 31, wid = tid >> 5;
    int warp_m = wid >> 2, warp_n = wid & 3;     // G1: 2 x 4 warp grid

    // ---- build W0P: [br][warp_n][ks*4+nb][lane] uint2 = pair (kg, kg+4) ----
    // 8192 uint2 = 64 KB (full size this time)
    {
        uint2* w0p = (uint2*)(smem + SM_W0P);
        for (int idx = tid; idx < 8192; idx += NTHREADS) {
            int li = idx & 31, t = idx >> 5;
            int nb = t & 3, ks = (t >> 2) & 7, wn = (t >> 5) & 3, br = t >> 7;
            int kg = ks * 8 + (li & 3);
            int ng = wn * 32 + nb * 8 + (li >> 2);
            const float* w0 = br ? w0r : w0t;
            w0p[idx] = make_uint2(f2tf(w0[kg * 128 + ng]),
                                  f2tf(w0[(kg + 4) * 128 + ng]));
        }
    }

    // ---- build W1P (pair-packed tf32) + biases in smem ----
    {
#pragma unroll
        for (int br = 0; br < 2; br++) {
            uint32_t* dst = (uint32_t*)(smem + SM_W1P + br * 17408);
            const float* w1 = br ? w1r : w1t;
            for (int i = tid; i < 4096; i += NTHREADS) {
                int k = i >> 5, n = i & 31;
                int ks = k >> 3, km = k & 3, h = (k >> 2) & 1;
                dst[n * W1STRIDE + ks * 8 + km * 2 + h] = f2tf(w1[k * 32 + n]);
            }
        }
        float* b0s = (float*)(smem + SM_B0);
        float* b1s = (float*)(smem + SM_B1);
        if (tid < 128) { b0s[tid] = b0t[tid]; b0s[128 + tid] = b0r[tid]; }
        if (tid < 32)  { b1s[tid] = b1t[tid]; b1s[32 + tid]  = b1r[tid]; }
    }

    const float* b0s = (const float*)(smem + SM_B0);
    const float* b1s = (const float*)(smem + SM_B1);

    int T = (N + TILE_P - 1) / TILE_P;
    int tile = blockIdx.x;
    if (tile >= T) return;

    // ---- register prefetch of first tile ----
    float4 xr[8];
    int sidr = -1;
    {
        int p0 = tile * TILE_P;
        const float4* x4 = reinterpret_cast<const float4*>(x);
#pragma unroll
        for (int it = 0; it < 8; it++) {
            int idx = tid + it * NTHREADS;
            int p = idx >> 4, c4 = idx & 15;
            xr[it] = (p0 + p < N) ? x4[(size_t)(p0 + p) * 16 + c4]
                                  : make_float4(0.f, 0.f, 0.f, 0.f);
        }
        if (tid < TILE_P) sidr = (p0 + tid < N) ? seg[p0 + tid] : -1;
    }
    __syncthreads();   // W0P / W1P / biases ready

    // ldmatrix lane-address components (row, 16B-chunk select)
    const int am = (lane & 7) + ((lane >> 3) & 1) * 8;
    const int ak = (lane >> 4) * 16;

    for (; tile < T; tile += GRID_MAIN) {
        // ---- store prefetched x tile (tf32-rounded) + sid ----
#pragma unroll
        for (int it = 0; it < 8; it++) {
            int idx = tid + it * NTHREADS;
            int p = idx >> 4, c4 = idx & 15;
            float4 v = xr[it];
            uint4 o = make_uint4(f2tf(v.x), f2tf(v.y), f2tf(v.z), f2tf(v.w));
            *(uint4*)(smem + SM_X + (p * XSTRIDE + c4 * 4) * 4) = o;
        }
        if (tid < TILE_P) ((int*)(smem + SM_SID))[tid] = sidr;
        __syncthreads();

        // ---- prefetch next tile into regs (overlaps compute) ----
        int nt = tile + GRID_MAIN;
        if (nt < T) {
            int p0 = nt * TILE_P;
            const float4* x4 = reinterpret_cast<const float4*>(x);
#pragma unroll
            for (int it = 0; it < 8; it++) {
                int idx = tid + it * NTHREADS;
                int p = idx >> 4, c4 = idx & 15;
                xr[it] = (p0 + p < N) ? x4[(size_t)(p0 + p) * 16 + c4]
                                      : make_float4(0.f, 0.f, 0.f, 0.f);
            }
            if (tid < TILE_P) sidr = (p0 + tid < N) ? seg[p0 + tid] : -1;
        }

#pragma unroll 1
        for (int br = 0; br < 2; br++) {
            // ---- reload this branch's B1 fragments from W0P (32 LDS.64) ----
            uint2 B1[8][4];
            {
                const uint2* w0p = (const uint2*)(smem + SM_W0P) +
                                   (br * 4 + warp_n) * 1024;
#pragma unroll
                for (int t = 0; t < 32; t++)
                    B1[t >> 2][t & 3] = w0p[t * 32 + lane];
            }

            // ============ GEMM1: X[128x64] @ W0 -> relu -> H1 (tf32) ========
            // warp owns rows [warp_m*64, +64) x cols [warp_n*32, +32)
#pragma unroll 1
            for (int mb = 0; mb < 4; mb++) {
                int rowb = warp_m * 64 + mb * 16;
                uint32_t A[8][4];
#pragma unroll
                for (int ks = 0; ks < 8; ks++)
                    ldsm_x4(A[ks], sb + SM_X + (rowb + am) * 272 + ks * 32 + ak);
                float d[4][4] = {{0.f, 0.f, 0.f, 0.f}, {0.f, 0.f, 0.f, 0.f},
                                 {0.f, 0.f, 0.f, 0.f}, {0.f, 0.f, 0.f, 0.f}};
#pragma unroll
                for (int ks = 0; ks < 8; ks++)
#pragma unroll
                    for (int nb = 0; nb < 4; nb++)
                        mma_tf32(d[nb], A[ks], B1[ks][nb].x, B1[ks][nb].y);
                // epilogue: bias + relu + tf32-round -> H1
                int pr = rowb + (lane >> 2);
#pragma unroll
                for (int nb = 0; nb < 4; nb++) {
                    int j0 = warp_n * 32 + nb * 8 + (lane & 3) * 2;
                    float c0 = b0s[br * 128 + j0], c1 = b0s[br * 128 + j0 + 1];
                    uint2 o0 = make_uint2(f2tf(fmaxf(d[nb][0] + c0, 0.f)),
                                          f2tf(fmaxf(d[nb][1] + c1, 0.f)));
                    *(uint2*)(smem + SM_H1 + (pr * H1STRIDE + j0) * 4) = o0;
                    uint2 o1 = make_uint2(f2tf(fmaxf(d[nb][2] + c0, 0.f)),
                                          f2tf(fmaxf(d[nb][3] + c1, 0.f)));
                    *(uint2*)(smem + SM_H1 + ((pr + 8) * H1STRIDE + j0) * 4) = o1;
                }
            }
            __syncthreads();

            // ============ GEMM2: H1[128x128] @ W1 -> relu -> H2 =============
            // warp owns 16 rows (mb = wid), all 32 cols
            float d2[4][4] = {{0.f, 0.f, 0.f, 0.f}, {0.f, 0.f, 0.f, 0.f},
                              {0.f, 0.f, 0.f, 0.f}, {0.f, 0.f, 0.f, 0.f}};
            {
                // generic pointer base for C++ derefs (NOT the cvta.to.shared int)
                const char* w1pg = smem + SM_W1P + br * 17408;
#pragma unroll 1
                for (int ks = 0; ks < 16; ks++) {
                    uint32_t A2[4];
                    ldsm_x4(A2, sb + SM_H1 + (wid * 16 + am) * 528 + ks * 32 + ak);
#pragma unroll
                    for (int nb = 0; nb < 4; nb++) {
                        int n = nb * 8 + (lane >> 2);
                        uint2 b = *(const uint2*)(w1pg +
                            (n * W1STRIDE + ks * 8 + (lane & 3) * 2) * 4);
                        mma_tf32(d2[nb], A2, b.x, b.y);
                    }
                }
            }
            {
                float* h2 = (float*)(smem + SM_H2);
                int pr = wid * 16 + (lane >> 2);
#pragma unroll
                for (int nb = 0; nb < 4; nb++) {
                    int j = nb * 8 + (lane & 3) * 2;
                    float c0 = b1s[br * 32 + j], c1 = b1s[br * 32 + j + 1];
                    h2[pr * 32 + j]           = fmaxf(d2[nb][0] + c0, 0.f);
                    h2[pr * 32 + j + 1]       = fmaxf(d2[nb][1] + c1, 0.f);
                    h2[(pr + 8) * 32 + j]     = fmaxf(d2[nb][2] + c0, 0.f);
                    h2[(pr + 8) * 32 + j + 1] = fmaxf(d2[nb][3] + c1, 0.f);
                }
            }
            __syncthreads();   // H2 complete for this branch

            // ---- per-branch sorted-run reduction: 32 features x 8 chunks ----
            {
                int f = tid & 31, q = tid >> 5;     // 8 chunks of 16 points
                const float* src = (const float*)(smem + SM_H2);
                float* dst = br ? g_seg_r : g_seg_t;
                const int* sid = (const int*)(smem + SM_SID);
                int cur = -1; float acc = 0.f;
#pragma unroll 1
                for (int p = q * 16; p < q * 16 + 16; ++p) {
                    int s = sid[p];
                    if (s != cur) {
                        if (cur >= 0) atomicAdd(&dst[cur * 32 + f], acc);
                        cur = s; acc = 0.f;
                    }
                    if (s >= 0) acc += src[p * 32 + f];
                }
                if (cur >= 0) atomicAdd(&dst[cur * 32 + f], acc);
            }
            __syncthreads();   // reduction done; H1/H2 free for next branch
        }
    }
}

// ============================ head kernel (2 threads/segment) ==============
#define HS_F0   0
#define HS_C0   2048
#define HS_B0   4096
#define HS_CT1  6144
#define HS_F0B  8192
#define HS_C0B  8256
#define HS_B0B  8320
#define HS_F1   8384
#define HS_C1   8448
#define HS_B1   8512
#define HS_CT0  8576
#define HS_CT0B 8768
#define HS_CT1B 8832
#define HS_POL  8864
#define HS_SCAL 8928
#define HS_SIZE 8936

__device__ __forceinline__ void copy4h(float* dst, const float* __restrict__ src,
                                       int n, int tid) {
    for (int i = tid; i < (n >> 2); i += 256)
        reinterpret_cast<float4*>(dst)[i] =
            reinterpret_cast<const float4*>(src)[i];
}

__global__ __launch_bounds__(256)
void head_kernel(const float* __restrict__ fwd0_w, const float* __restrict__ fwd0_b,
                 const float* __restrict__ fwd1_w, const float* __restrict__ fwd1_b,
                 const float* __restrict__ com0_w, const float* __restrict__ com0_b,
                 const float* __restrict__ com1_w, const float* __restrict__ com1_b,
                 const float* __restrict__ bwd0_w, const float* __restrict__ bwd0_b,
                 const float* __restrict__ bwd1_w, const float* __restrict__ bwd1_b,
                 const float* __restrict__ cost0_w, const float* __restrict__ cost0_b,
                 const float* __restrict__ cost1_w, const float* __restrict__ cost1_b,
                 const float* __restrict__ pol_w, const float* __restrict__ pol_b,
                 float* __restrict__ out) {
    __shared__ __align__(16) float sw[HS_SIZE];
    int tid = threadIdx.x;
    copy4h(sw + HS_F0,   fwd0_w, 2048, tid);
    copy4h(sw + HS_C0,   com0_w, 2048, tid);
    copy4h(sw + HS_B0,   bwd0_w, 2048, tid);
    copy4h(sw + HS_CT1,  cost1_w, 2048, tid);
    copy4h(sw + HS_F0B,  fwd0_b, 64, tid);
    copy4h(sw + HS_C0B,  com0_b, 64, tid);
    copy4h(sw + HS_B0B,  bwd0_b, 64, tid);
    copy4h(sw + HS_F1,   fwd1_w, 64, tid);
    copy4h(sw + HS_C1,   com1_w, 64, tid);
    copy4h(sw + HS_B1,   bwd1_w, 64, tid);
    copy4h(sw + HS_CT0,  cost0_w, 192, tid);
    copy4h(sw + HS_CT0B, cost0_b, 64, tid);
    copy4h(sw + HS_CT1B, cost1_b, 32, tid);
    copy4h(sw + HS_POL,  pol_w, 64, tid);
    if (tid == 0) {
        sw[HS_SCAL + 0] = fwd1_b[0];
        sw[HS_SCAL + 1] = com1_b[0];
        sw[HS_SCAL + 2] = bwd1_b[0];
        sw[HS_SCAL + 3] = pol_b[0];
    }
    __syncthreads();

    int idx = blockIdx.x * 256 + tid;       // 0 .. 2*SSEG-1
    int s = idx >> 1, half = idx & 1;       // 2 threads per segment

    float t[32], r[32];
#pragma unroll
    for (int i = 0; i < 8; i++) {
        float4 v = *reinterpret_cast<const float4*>(&g_seg_t[(size_t)s * 32 + i * 4]);
        t[i * 4] = v.x; t[i * 4 + 1] = v.y; t[i * 4 + 2] = v.z; t[i * 4 + 3] = v.w;
        float4 u = *reinterpret_cast<const float4*>(&g_seg_r[(size_t)s * 32 + i * 4]);
        r[i * 4] = u.x; r[i * 4 + 1] = u.y; r[i * 4 + 2] = u.z; r[i * 4 + 3] = u.w;
    }

    // half of each head's 64 hidden units
    auto headp = [&](const float* w0, const float* b0, const float* w1) -> float {
        float o = 0.f;
#pragma unroll
        for (int q = 0; q < 8; q++) {
            int i4 = half * 8 + q;
            float4 hb = *reinterpret_cast<const float4*>(&b0[i4 * 4]);
            float h0 = hb.x, h1 = hb.y, h2 = hb.z, h3 = hb.w;
#pragma unroll
            for (int k = 0; k < 32; k++) {
                float4 w = *reinterpret_cast<const float4*>(&w0[k * 64 + i4 * 4]);
                h0 = fmaf(t[k], w.x, h0); h1 = fmaf(t[k], w.y, h1);
                h2 = fmaf(t[k], w.z, h2); h3 = fmaf(t[k], w.w, h3);
            }
            float4 wv = *reinterpret_cast<const float4*>(&w1[i4 * 4]);
            o += fmaxf(h0, 0.f) * wv.x + fmaxf(h1, 0.f) * wv.y +
                 fmaxf(h2, 0.f) * wv.z + fmaxf(h3, 0.f) * wv.w;
        }
        return o;
    };

    float fc = headp(sw + HS_F0, sw + HS_F0B, sw + HS_F1);
    float cc = headp(sw + HS_C0, sw + HS_C0B, sw + HS_C1);
    float bc = headp(sw + HS_B0, sw + HS_B0B, sw + HS_B1);
    fc += __shfl_xor_sync(0xFFFFFFFFu, fc, 1); fc += sw[HS_SCAL + 0];
    cc += __shfl_xor_sync(0xFFFFFFFFu, cc, 1); cc += sw[HS_SCAL + 1];
    bc += __shfl_xor_sync(0xFFFFFFFFu, bc, 1); bc += sw[HS_SCAL + 2];

    // cost MLP layer 1: this thread's 32 of 64 hidden units
    float c1h[32];
#pragma unroll
    for (int q = 0; q < 8; q++) {
        int i4 = half * 8 + q;
        float4 a  = *reinterpret_cast<const float4*>(&sw[HS_CT0B + i4 * 4]);
        float4 w0 = *reinterpret_cast<const float4*>(&sw[HS_CT0 + 0 * 64 + i4 * 4]);
        float4 w1 = *reinterpret_cast<const float4*>(&sw[HS_CT0 + 1 * 64 + i4 * 4]);
        float4 w2 = *reinterpret_cast<const float4*>(&sw[HS_CT0 + 2 * 64 + i4 * 4]);
        a.x = fmaf(fc, w0.x, fmaf(cc, w1.x, fmaf(bc, w2.x, a.x)));
        a.y = fmaf(fc, w0.y, fmaf(cc, w1.y, fmaf(bc, w2.y, a.y)));
        a.z = fmaf(fc, w0.z, fmaf(cc, w1.z, fmaf(bc, w2.z, a.z)));
        a.w = fmaf(fc, w0.w, fmaf(cc, w1.w, fmaf(bc, w2.w, a.w)));
        c1h[q * 4 + 0] = fmaxf(a.x, 0.f);
        c1h[q * 4 + 1] = fmaxf(a.y, 0.f);
        c1h[q * 4 + 2] = fmaxf(a.z, 0.f);
        c1h[q * 4 + 3] = fmaxf(a.w, 0.f);
    }

    // cost layer 2 partials over this thread's k-half, all 32 outputs
    float pj[32];
#pragma unroll
    for (int j = 0; j < 32; j++) pj[j] = 0.f;
#pragma unroll
    for (int k = 0; k < 32; k++) {
        int kg = half * 32 + k;
        const float* wr = &sw[HS_CT1 + kg * 32];
#pragma unroll
        for (int j = 0; j < 32; j++) pj[j] = fmaf(c1h[k], wr[j], pj[j]);
    }
#pragma unroll
    for (int j = 0; j < 32; j++)
        pj[j] += __shfl_xor_sync(0xFFFFFFFFu, pj[j], 1);

    // policy dot: split r-part and c-part by half
    float logit = 0.f;
#pragma unroll
    for (int k = 0; k < 16; k++) {
        int kg = half * 16 + k;
        logit = fmaf(r[kg], sw[HS_POL + kg], logit);
    }
#pragma unroll
    for (int j = 0; j < 16; j++) {
        int jg = half * 16 + j;
        float v = fmaxf(pj[jg] + sw[HS_CT1B + jg], 0.f);
        logit = fmaf(v, sw[HS_POL + 32 + jg], logit);
    }
    logit += __shfl_xor_sync(0xFFFFFFFFu, logit, 1);
    if (half == 0) out[s] = logit + sw[HS_SCAL + 3];
}

// ============================ launcher =====================================
extern "C" void kernel_launch(void* const* d_in, const int* in_sizes, int n_in,
                              void* d_out, int out_size) {
    int off = (in_sizes[2] == 1 && in_sizes[3] == 1) ? 4 : 2;
    const float* x   = (const float*)d_in[0];
    const int*   seg = (const int*)d_in[1];
    const float* tfc0_w = (const float*)d_in[off + 0];
    const float* tfc0_b = (const float*)d_in[off + 1];
    const float* tfc1_w = (const float*)d_in[off + 2];
    const float* tfc1_b = (const float*)d_in[off + 3];
    const float* fwd0_w = (const float*)d_in[off + 4];
    const float* fwd0_b = (const float*)d_in[off + 5];
    const float* fwd1_w = (const float*)d_in[off + 6];
    const float* fwd1_b = (const float*)d_in[off + 7];
    const float* com0_w = (const float*)d_in[off + 8];
    const float* com0_b = (const float*)d_in[off + 9];
    const float* com1_w = (const float*)d_in[off + 10];
    const float* com1_b = (const float*)d_in[off + 11];
    const float* bwd0_w = (const float*)d_in[off + 12];
    const float* bwd0_b = (const float*)d_in[off + 13];
    const float* bwd1_w = (const float*)d_in[off + 14];
    const float* bwd1_b = (const float*)d_in[off + 15];
    const float* rl0_w  = (const float*)d_in[off + 16];
    const float* rl0_b  = (const float*)d_in[off + 17];
    const float* rl1_w  = (const float*)d_in[off + 18];
    const float* rl1_b  = (const float*)d_in[off + 19];
    const float* cost0_w = (const float*)d_in[off + 20];
    const float* cost0_b = (const float*)d_in[off + 21];
    const float* cost1_w = (const float*)d_in[off + 22];
    const float* cost1_b = (const float*)d_in[off + 23];
    const float* pol_w   = (const float*)d_in[off + 24];
    const float* pol_b   = (const float*)d_in[off + 25];

    int N = in_sizes[0] / FDIM;

    cudaFuncSetAttribute(mlp_mma_kernel,
                         cudaFuncAttributeMaxDynamicSharedMemorySize, SMEM_BYTES);

    zero_seg_kernel<<<(SSEG * 32 + 255) / 256, 256>>>();

    mlp_mma_kernel<<<GRID_MAIN, NTHREADS, SMEM_BYTES>>>(
        x, seg, tfc0_w, rl0_w, tfc1_w, rl1_w,
        tfc0_b, rl0_b, tfc1_b, rl1_b, N);

    head_kernel<<<(2 * SSEG) / 256, 256>>>(
        fwd0_w, fwd0_b, fwd1_w, fwd1_b,
        com0_w, com0_b, com1_w, com1_b,
        bwd0_w, bwd0_b, bwd1_w, bwd1_b,
        cost0_w, cost0_b, cost1_w, cost1_b,
        pol_w, pol_b, (float*)d_out);
}